// round 15
// baseline (speedup 1.0000x reference)
#include <cuda_runtime.h>
#include <cuda_bf16.h>
#include <math.h>
#include <stdint.h>

#define SEQ   1024
#define EMB   2880
#define NH    64
#define NKV   8
#define HDIM  64
#define HD    4096
#define KVD   512
#define WIN   128
#define QT    8
#define NKEY  135
#define KSTR  68
#define VSTR  140   // vT row stride: 140 mod 32 = 12 -> conflict-free float4 phases

// ---------------- device-global scratch ----------------
__device__ __align__(256) float g_q[SEQ*HD];
__device__ __align__(256) float g_k[SEQ*KVD];
__device__ __align__(256) float g_v[SEQ*KVD];
__device__ __align__(256) float g_cos[SEQ*32], g_sin[SEQ*32];
__device__ __align__(256) __nv_bfloat16 g_xhi[SEQ*EMB],  g_xlo[SEQ*EMB];
__device__ __align__(256) __nv_bfloat16 g_ahi[SEQ*HD],   g_alo[SEQ*HD];
__device__ __align__(256) __nv_bfloat16 g_Wqhi[HD*EMB],  g_Wqlo[HD*EMB];
__device__ __align__(256) __nv_bfloat16 g_Wkhi[KVD*EMB], g_Wklo[KVD*EMB];
__device__ __align__(256) __nv_bfloat16 g_Wvhi[KVD*EMB], g_Wvlo[KVD*EMB];
__device__ __align__(256) __nv_bfloat16 g_Wohi[EMB*HD],  g_Wolo[EMB*HD];

// ---------------- helpers ----------------
__device__ __forceinline__ uint32_t smem_u32(const void* p) {
    uint32_t a;
    asm("{ .reg .u64 t; cvta.to.shared.u64 t, %1; cvt.u32.u64 %0, t; }"
        : "=r"(a) : "l"(p));
    return a;
}

#define SWZ(o) ((o) ^ (((o) >> 3) & 0x70))

#define LDSM4(d, addr) \
    asm volatile("ldmatrix.sync.aligned.m8n8.x4.shared.b16 {%0,%1,%2,%3}, [%4];" \
        : "=r"((d)[0]), "=r"((d)[1]), "=r"((d)[2]), "=r"((d)[3]) : "r"(addr))

#define MMA16816(d, a, b0, b1) \
    asm volatile("mma.sync.aligned.m16n8k16.row.col.f32.bf16.bf16.f32 " \
        "{%0,%1,%2,%3}, {%4,%5,%6,%7}, {%8,%9}, {%0,%1,%2,%3};" \
        : "+f"((d)[0]), "+f"((d)[1]), "+f"((d)[2]), "+f"((d)[3]) \
        : "r"((a)[0]), "r"((a)[1]), "r"((a)[2]), "r"((a)[3]), "r"(b0), "r"(b1))

#define CP16(dst, src) \
    asm volatile("cp.async.cg.shared.global [%0], [%1], 16;" \
        :: "r"(dst), "l"((const void*)(src)) : "memory")
#define CP_COMMIT() asm volatile("cp.async.commit_group;" ::: "memory")
#define CP_WAIT0()  asm volatile("cp.async.wait_group 0;" ::: "memory")

// ---------------- fused split pre-pass: fp32 -> bf16 hi + lo ----------------
#define N4_X   (SEQ*EMB/4)
#define N4_WQ  (HD*EMB/4)
#define N4_WKV (KVD*EMB/4)
#define N4_WO  (EMB*HD/4)
#define N4_TOT (N4_X + N4_WQ + 2*N4_WKV + N4_WO)

__global__ void split_all(const float* __restrict__ x,  const float* __restrict__ Wq,
                          const float* __restrict__ Wk, const float* __restrict__ Wv,
                          const float* __restrict__ Wo) {
    int t = blockIdx.x * blockDim.x + threadIdx.x;
    const float* src; __nv_bfloat16 *hi, *lo; int i4;
    if (t < N4_X)                         { i4 = t;                           src = x;  hi = g_xhi;  lo = g_xlo;  }
    else if (t < N4_X + N4_WQ)            { i4 = t - N4_X;                    src = Wq; hi = g_Wqhi; lo = g_Wqlo; }
    else if (t < N4_X + N4_WQ + N4_WKV)   { i4 = t - N4_X - N4_WQ;            src = Wk; hi = g_Wkhi; lo = g_Wklo; }
    else if (t < N4_X + N4_WQ + 2*N4_WKV) { i4 = t - N4_X - N4_WQ - N4_WKV;   src = Wv; hi = g_Wvhi; lo = g_Wvlo; }
    else                                  { i4 = t - N4_X - N4_WQ - 2*N4_WKV; src = Wo; hi = g_Wohi; lo = g_Wolo; }
    int i = i4 * 4;
    float4 v = *(const float4*)(src + i);
    __nv_bfloat162 h01 = __floats2bfloat162_rn(v.x, v.y);
    __nv_bfloat162 h23 = __floats2bfloat162_rn(v.z, v.w);
    __nv_bfloat162 l01 = __floats2bfloat162_rn(v.x - __bfloat162float(h01.x),
                                               v.y - __bfloat162float(h01.y));
    __nv_bfloat162 l23 = __floats2bfloat162_rn(v.z - __bfloat162float(h23.x),
                                               v.w - __bfloat162float(h23.y));
    *(uint2*)(hi + i) = make_uint2(*(uint32_t*)&h01, *(uint32_t*)&h23);
    *(uint2*)(lo + i) = make_uint2(*(uint32_t*)&l01, *(uint32_t*)&l23);
}

// ---------------- split-bf16 HMMA GEMM (unchanged from R11) ----------------
#define GKC 32
#define A_BYTES  (128*64)
#define B_BYTES  (64*64)
#define OFF_ALO  A_BYTES
#define OFF_BHI  (2*A_BYTES)
#define OFF_BLO  (2*A_BYTES + B_BYTES)
#define STAGE_BYTES (2*A_BYTES + 2*B_BYTES)
#define GSMEM (2*STAGE_BYTES + 256)

__device__ __forceinline__ void gemm_core(
        const __nv_bfloat16* __restrict__ Ahi, const __nv_bfloat16* __restrict__ Alo, int lda,
        const __nv_bfloat16* __restrict__ Bhi, const __nv_bfloat16* __restrict__ Blo, int ldb,
        const float* __restrict__ bias,
        float* __restrict__ C, int ldc, int K) {
    extern __shared__ char smem[];
    uint32_t sb = smem_u32(smem);
    float* bias_sh = (float*)(smem + 2 * STAGE_BYTES);

    int tid  = threadIdx.x;
    int lane = tid & 31;
    int w    = tid >> 5;
    int bm   = blockIdx.y * 128;
    int wm   = (w >> 1) * 64;
    int wn   = (w & 1) * 32;

    if (tid < 64) bias_sh[tid] = bias[tid];

    const __nv_bfloat16* pAh = Ahi + (size_t)bm * lda;
    const __nv_bfloat16* pAl = Alo + (size_t)bm * lda;

    int rr_ = tid >> 2, cc_ = tid & 3;
    uint32_t dA0 = (uint32_t)SWZ(rr_ * 64 + cc_ * 16);
    uint32_t dA1 = (uint32_t)SWZ((rr_ + 32) * 64 + cc_ * 16);
    uint32_t dA2 = (uint32_t)SWZ((rr_ + 64) * 64 + cc_ * 16);
    uint32_t dA3 = (uint32_t)SWZ((rr_ + 96) * 64 + cc_ * 16);
    uint32_t dB0 = dA0, dB1 = dA1;

#define LOAD_STAGE(soff, kt) do {                                            \
    const __nv_bfloat16* sAh = pAh + (size_t)rr_ * lda + (kt) + cc_ * 8;     \
    const __nv_bfloat16* sAl = pAl + (size_t)rr_ * lda + (kt) + cc_ * 8;     \
    uint32_t base_ = sb + (soff);                                            \
    CP16(base_ + dA0,            sAh);                                       \
    CP16(base_ + dA1,            sAh + (size_t)32 * lda);                    \
    CP16(base_ + dA2,            sAh + (size_t)64 * lda);                    \
    CP16(base_ + dA3,            sAh + (size_t)96 * lda);                    \
    CP16(base_ + OFF_ALO + dA0,  sAl);                                       \
    CP16(base_ + OFF_ALO + dA1,  sAl + (size_t)32 * lda);                    \
    CP16(base_ + OFF_ALO + dA2,  sAl + (size_t)64 * lda);                    \
    CP16(base_ + OFF_ALO + dA3,  sAl + (size_t)96 * lda);                    \
    const __nv_bfloat16* sBh = Bhi + (size_t)rr_ * ldb + (kt) + cc_ * 8;     \
    const __nv_bfloat16* sBl = Blo + (size_t)rr_ * ldb + (kt) + cc_ * 8;     \
    CP16(base_ + OFF_BHI + dB0,  sBh);                                       \
    CP16(base_ + OFF_BHI + dB1,  sBh + (size_t)32 * ldb);                    \
    CP16(base_ + OFF_BLO + dB0,  sBl);                                       \
    CP16(base_ + OFF_BLO + dB1,  sBl + (size_t)32 * ldb);                    \
} while (0)

    int r = lane & 7, g = lane >> 3;
    int a_row = wm + ((g & 1) << 3) + r;
    int a_o   = a_row * 64 + (g >> 1) * 16;
    int b_row = wn + (((g >> 1) & 1) << 3) + r;
    int b_o   = b_row * 64 + (g & 1) * 16;
    uint32_t a_sw0 = (uint32_t)SWZ(a_o);
    uint32_t a_sw1 = (uint32_t)SWZ(a_o + 32);
    uint32_t b_sw0 = (uint32_t)SWZ(b_o);
    uint32_t b_sw1 = (uint32_t)SWZ(b_o + 32);

    float acc[4][4][4];
#pragma unroll
    for (int i = 0; i < 4; i++)
#pragma unroll
        for (int j = 0; j < 4; j++)
#pragma unroll
            for (int q = 0; q < 4; q++) acc[i][j][q] = 0.0f;

    int NC = K / GKC;
    LOAD_STAGE(0, 0);
    CP_COMMIT();

    for (int c = 0; c < NC; c++) {
        CP_WAIT0();
        __syncthreads();
        if (c + 1 < NC) { LOAD_STAGE(((c + 1) & 1) * STAGE_BYTES, (c + 1) * GKC); }
        CP_COMMIT();

        uint32_t buf = sb + (uint32_t)((c & 1) * STAGE_BYTES);
#pragma unroll
        for (int ks = 0; ks < 2; ks++) {
            uint32_t asw = (ks == 0) ? a_sw0 : a_sw1;
            uint32_t bsw = (ks == 0) ? b_sw0 : b_sw1;
            uint32_t bH[2][4], bL[2][4];
#pragma unroll
            for (int nf2 = 0; nf2 < 2; nf2++) {
                uint32_t bd = buf + OFF_BHI + bsw + (uint32_t)(nf2 * 1024);
                LDSM4(bH[nf2], bd);
                LDSM4(bL[nf2], bd + B_BYTES);
            }
#pragma unroll
            for (int mf = 0; mf < 4; mf++) {
                uint32_t aH[4], aL[4];
                uint32_t ad = buf + asw + (uint32_t)(mf * 1024);
                LDSM4(aH, ad);
                LDSM4(aL, ad + OFF_ALO);
#pragma unroll
                for (int nf = 0; nf < 4; nf++) {
                    uint32_t b0h = bH[nf >> 1][(nf & 1) * 2];
                    uint32_t b1h = bH[nf >> 1][(nf & 1) * 2 + 1];
                    uint32_t b0l = bL[nf >> 1][(nf & 1) * 2];
                    uint32_t b1l = bL[nf >> 1][(nf & 1) * 2 + 1];
                    MMA16816(acc[mf][nf], aH, b0h, b1h);
                    MMA16816(acc[mf][nf], aL, b0h, b1h);
                    MMA16816(acc[mf][nf], aH, b0l, b1l);
                }
            }
        }
        __syncthreads();
    }
#undef LOAD_STAGE

    int rr = lane >> 2, cc = (lane & 3) * 2;
#pragma unroll
    for (int mf = 0; mf < 4; mf++) {
        int row0 = bm + wm + mf * 16 + rr;
#pragma unroll
        for (int nf = 0; nf < 4; nf++) {
            int col = wn + nf * 8 + cc;
            float b0 = bias_sh[col], b1 = bias_sh[col + 1];
            float2 v0 = make_float2(acc[mf][nf][0] + b0, acc[mf][nf][1] + b1);
            float2 v1 = make_float2(acc[mf][nf][2] + b0, acc[mf][nf][3] + b1);
            *(float2*)(C + (size_t)row0 * ldc + col)       = v0;
            *(float2*)(C + (size_t)(row0 + 8) * ldc + col) = v1;
        }
    }
}

__global__ void __launch_bounds__(128, 4)
qkv_gemm(const float* __restrict__ bq, const float* __restrict__ bk,
         const float* __restrict__ bv) {
    int nt = blockIdx.x;
    const __nv_bfloat16 *Bh, *Bl; const float* bi; float* C; int ldc;
    if (nt < 64) {
        Bh = g_Wqhi + (size_t)nt * 64 * EMB; Bl = g_Wqlo + (size_t)nt * 64 * EMB;
        bi = bq + nt * 64; C = g_q + nt * 64; ldc = HD;
    } else if (nt < 72) {
        int t = nt - 64;
        Bh = g_Wkhi + (size_t)t * 64 * EMB; Bl = g_Wklo + (size_t)t * 64 * EMB;
        bi = bk + t * 64; C = g_k + t * 64; ldc = KVD;
    } else {
        int t = nt - 72;
        Bh = g_Wvhi + (size_t)t * 64 * EMB; Bl = g_Wvlo + (size_t)t * 64 * EMB;
        bi = bv + t * 64; C = g_v + t * 64; ldc = KVD;
    }
    gemm_core(g_xhi, g_xlo, EMB, Bh, Bl, EMB, bi, C, ldc, EMB);
}

__global__ void __launch_bounds__(128, 4)
oproj_gemm(const float* __restrict__ bo, float* __restrict__ out) {
    int n0 = blockIdx.x * 64;
    gemm_core(g_ahi, g_alo, HD,
              g_Wohi + (size_t)n0 * HD, g_Wolo + (size_t)n0 * HD, HD,
              bo + n0, out + n0, EMB, HD);
}

// ---------------- RoPE table (YaRN): cos/sin[SEQ][32] ----------------
__global__ void rope_table(const int* __restrict__ positions) {
    int s = blockIdx.x;
    int i = threadIdx.x;   // 0..31
    float i2 = 2.0f * (float)i;
    float pf = powf(150000.0f, i2 / 64.0f);
    double lbase = 2.0 * log(150000.0);
    double low  = 64.0 * log(4096.0 / (32.0 * 2.0 * M_PI)) / lbase;
    double high = 64.0 * log(4096.0 / (1.0  * 2.0 * M_PI)) / lbase;
    if (low  < 0.0)  low  = 0.0;
    if (high > 31.0) high = 31.0;
    float ramp = ((float)i - (float)low) / (float)(high - low);
    ramp = fminf(fmaxf(ramp, 0.0f), 1.0f);
    float invf = (1.0f / (32.0f * pf)) * ramp + (1.0f / pf) * (1.0f - ramp);
    float mscale = 0.1f * logf(32.0f) + 1.0f;
    float ang = (float)positions[s] * invf;
    g_cos[s * 32 + i] = cosf(ang) * mscale;
    g_sin[s * 32 + i] = sinf(ang) * mscale;
}

// ---------------- Attention: fused RoPE staging, transposed V ----------------
__global__ void attn_kernel(const float* __restrict__ sinks) {
    extern __shared__ float asmem[];
    float* k_sh = asmem;                     // NKEY*KSTR  (9180)
    float* v_sh = k_sh + NKEY * KSTR;        // 64*VSTR    (8960) transposed [d][t]
    float* q_sh = v_sh + 64 * VSTR;          // QT*512     (4096)
    float* p_sh = q_sh + QT * 512;           // 8*144      (1152)

    int kvh  = blockIdx.x;
    int q0   = blockIdx.y * QT;
    int base = q0 - (WIN - 1);
    int tid  = threadIdx.x;
    int w    = tid >> 5;
    int lane = tid & 31;

    // K staging with fused RoPE (dims d / d+32 pairs)
    for (int it = tid; it < NKEY * 8; it += 256) {
        int row = it >> 3, d4 = it & 7;
        int sg = base + row;
        float4 a = make_float4(0.f, 0.f, 0.f, 0.f);
        float4 b = make_float4(0.f, 0.f, 0.f, 0.f);
        if (sg >= 0) {
            const float* kb = g_k + (size_t)sg * KVD + kvh * HDIM;
            float4 xa = *(const float4*)(kb + d4 * 4);
            float4 xb = *(const float4*)(kb + 32 + d4 * 4);
            float4 cs = *(const float4*)(g_cos + sg * 32 + d4 * 4);
            float4 sn = *(const float4*)(g_sin + sg * 32 + d4 * 4);
            a.x = xa.x * cs.x - xb.x * sn.x;  b.x = xb.x * cs.x + xa.x * sn.x;
            a.y = xa.y * cs.y - xb.y * sn.y;  b.y = xb.y * cs.y + xa.y * sn.y;
            a.z = xa.z * cs.z - xb.z * sn.z;  b.z = xb.z * cs.z + xa.z * sn.z;
            a.w = xa.w * cs.w - xb.w * sn.w;  b.w = xb.w * cs.w + xa.w * sn.w;
        }
        *(float4*)(k_sh + row * KSTR + d4 * 4)      = a;
        *(float4*)(k_sh + row * KSTR + 32 + d4 * 4) = b;
    }
    // V staging: transpose to vT[d][row]
    for (int it = tid; it < NKEY * 16; it += 256) {
        int row = it >> 4, d4 = it & 15;
        int sg = base + row;
        float4 v = make_float4(0.f, 0.f, 0.f, 0.f);
        if (sg >= 0)
            v = *(const float4*)(g_v + (size_t)sg * KVD + kvh * HDIM + d4 * 4);
        v_sh[(d4 * 4 + 0) * VSTR + row] = v.x;
        v_sh[(d4 * 4 + 1) * VSTR + row] = v.y;
        v_sh[(d4 * 4 + 2) * VSTR + row] = v.z;
        v_sh[(d4 * 4 + 3) * VSTR + row] = v.w;
    }
    // zero vT pad columns 135..139 (avoid 0*NaN in PV tail)
    for (int it = tid; it < 64 * 5; it += 256) {
        int d = it / 5, c = NKEY + it % 5;
        v_sh[d * VSTR + c] = 0.0f;
    }
    // Q staging with fused RoPE
    for (int it = tid; it < QT * 8 * 8; it += 256) {
        int j = it >> 6, h = (it >> 3) & 7, d4 = it & 7;
        int pos = q0 + j;
        const float* qb = g_q + (size_t)pos * HD + (kvh * 8 + h) * HDIM;
        float4 xa = *(const float4*)(qb + d4 * 4);
        float4 xb = *(const float4*)(qb + 32 + d4 * 4);
        float4 cs = *(const float4*)(g_cos + pos * 32 + d4 * 4);
        float4 sn = *(const float4*)(g_sin + pos * 32 + d4 * 4);
        float4 a, b;
        a.x = xa.x * cs.x - xb.x * sn.x;  b.x = xb.x * cs.x + xa.x * sn.x;
        a.y = xa.y * cs.y - xb.y * sn.y;  b.y = xb.y * cs.y + xa.y * sn.y;
        a.z = xa.z * cs.z - xb.z * sn.z;  b.z = xb.z * cs.z + xa.z * sn.z;
        a.w = xa.w * cs.w - xb.w * sn.w;  b.w = xb.w * cs.w + xa.w * sn.w;
        *(float4*)(q_sh + j * 512 + h * 64 + d4 * 4)      = a;
        *(float4*)(q_sh + j * 512 + h * 64 + 32 + d4 * 4) = b;
    }
    __syncthreads();

    int h = kvh * 8 + w;
    float sinkv = sinks[h];
    float* pw = p_sh + w * 144;

    for (int j = 0; j < QT; j++) {
        const float4* q4 = (const float4*)(q_sh + j * 512 + w * 64);
        float4 qr[16];
#pragma unroll
        for (int d = 0; d < 16; d++) qr[d] = q4[d];

        float sc[4];
        bool  val[4];
        float mx = -INFINITY;
#pragma unroll
        for (int m = 0; m < 4; m++) {
            int off = j + lane + 32 * m;
            int sg  = base + off;
            val[m] = (sg >= 0);
            const float4* k4 = (const float4*)(k_sh + off * KSTR);
            float acc = 0.0f;
#pragma unroll
            for (int d = 0; d < 16; d++) {
                float4 kv = k4[d];
                acc += qr[d].x * kv.x + qr[d].y * kv.y
                     + qr[d].z * kv.z + qr[d].w * kv.w;
            }
            sc[m] = acc * 0.125f;
            if (val[m]) mx = fmaxf(mx, sc[m]);
        }
#pragma unroll
        for (int o = 16; o; o >>= 1) mx = fmaxf(mx, __shfl_xor_sync(0xFFFFFFFFu, mx, o));
        mx = fmaxf(mx, sinkv);

        float lsum = 0.0f;
        float p[4];
#pragma unroll
        for (int m = 0; m < 4; m++) {
            p[m] = val[m] ? __expf(sc[m] - mx) : 0.0f;
            lsum += p[m];
        }
#pragma unroll
        for (int o = 16; o; o >>= 1) lsum += __shfl_xor_sync(0xFFFFFFFFu, lsum, o);
        float inv = 1.0f / (lsum + __expf(sinkv - mx));

        // write probs into window-padded p_full[144]
#pragma unroll
        for (int m = 0; m < 4; m++)
            pw[j + lane + 32 * m] = p[m] * inv;
        if (j == 0) { if (lane < 16) pw[128 + lane] = 0.0f; }
        else        { if (lane == 0) pw[j - 1] = 0.0f; }
        __syncwarp();

        // PV: o[d] = sum_c p_full[c] * vT[d][c], d = lane / lane+32
        float o0 = 0.0f, o1 = 0.0f;
        const float4* pv4 = (const float4*)pw;
        const float* va = v_sh + lane * VSTR;
        const float* vb = v_sh + (lane + 32) * VSTR;
#pragma unroll 9
        for (int c4 = 0; c4 < 36; c4++) {
            float4 pp = pv4[c4];
            float4 a = *(const float4*)(va + c4 * 4);
            float4 b = *(const float4*)(vb + c4 * 4);
            o0 += pp.x * a.x + pp.y * a.y + pp.z * a.z + pp.w * a.w;
            o1 += pp.x * b.x + pp.y * b.y + pp.z * b.z + pp.w * b.w;
        }
        size_t ob = (size_t)(q0 + j) * HD + (size_t)h * HDIM;
        __nv_bfloat16 h0 = __float2bfloat16(o0);
        __nv_bfloat16 h1 = __float2bfloat16(o1);
        g_ahi[ob + lane]      = h0;
        g_ahi[ob + lane + 32] = h1;
        g_alo[ob + lane]      = __float2bfloat16(o0 - __bfloat162float(h0));
        g_alo[ob + lane + 32] = __float2bfloat16(o1 - __bfloat162float(h1));
        __syncwarp();
    }
}

// ---------------- Launch ----------------
extern "C" void kernel_launch(void* const* d_in, const int* in_sizes, int n_in,
                              void* d_out, int out_size) {
    (void)in_sizes; (void)n_in; (void)out_size;
    const float* x     = (const float*)d_in[0];
    const int*   pos   = (const int*)  d_in[1];
    const float* Wq    = (const float*)d_in[2];
    const float* bq    = (const float*)d_in[3];
    const float* Wk    = (const float*)d_in[4];
    const float* bk    = (const float*)d_in[5];
    const float* Wv    = (const float*)d_in[6];
    const float* bv    = (const float*)d_in[7];
    const float* Wo    = (const float*)d_in[8];
    const float* bo    = (const float*)d_in[9];
    const float* sinks = (const float*)d_in[10];
    float* out = (float*)d_out;

    size_t asz = (size_t)(NKEY * KSTR + 64 * VSTR + QT * 512 + 8 * 144) * sizeof(float);
    cudaFuncSetAttribute(qkv_gemm,   cudaFuncAttributeMaxDynamicSharedMemorySize, GSMEM);
    cudaFuncSetAttribute(oproj_gemm, cudaFuncAttributeMaxDynamicSharedMemorySize, GSMEM);
    cudaFuncSetAttribute(attn_kernel, cudaFuncAttributeMaxDynamicSharedMemorySize, (int)asz);

    split_all<<<N4_TOT / 256, 256>>>(x, Wq, Wk, Wv, Wo);
    rope_table<<<SEQ, 32>>>(pos);
    qkv_gemm<<<dim3(80, 8), 128, GSMEM>>>(bq, bk, bv);
    attn_kernel<<<dim3(NKV, SEQ / QT), 256, asz>>>(sinks);
    oproj_gemm<<<dim3(45, 8), 128, GSMEM>>>(bo, out);
}